// round 1
// baseline (speedup 1.0000x reference)
#include <cuda_runtime.h>
#include <math.h>

#define B_SZ   128
#define KDIM   4096
#define EMB    512
#define NNEG   2048
#define OUTW   (NNEG + 1)

// Scratch (static device globals — no allocation)
__device__ float g_hidden[B_SZ * KDIM];      // 2 MB
__device__ float g_part[8 * B_SZ * EMB];     // 2 MB (K-split partials for GEMM2)
__device__ float g_emb[B_SZ * EMB];          // 256 KB

// ---------------- packed f32x2 helpers (Blackwell FFMA2 path) ----------------
__device__ __forceinline__ unsigned long long pack2(float lo, float hi) {
    unsigned long long r;
    asm("mov.b64 %0, {%1, %2};" : "=l"(r) : "f"(lo), "f"(hi));
    return r;
}
__device__ __forceinline__ float2 unpack2(unsigned long long v) {
    float2 u;
    asm("mov.b64 {%0, %1}, %2;" : "=f"(u.x), "=f"(u.y) : "l"(v));
    return u;
}
__device__ __forceinline__ void ffma2(unsigned long long& d, unsigned long long a, unsigned long long b) {
    asm("fma.rn.f32x2 %0, %1, %2, %3;" : "=l"(d) : "l"(a), "l"(b), "l"(d));
}

// ---------------------------------------------------------------------------
// C[128, N-tile16] = A[128,K] @ B[N,K]^T (+bias), optional K-split on blockIdx.y
// (writes partial tile to C + blockIdx.y * 128 * ldc).
// BM=128, BN=16, BK=16, 256 threads; per-thread 2 row-pairs x 2 cols, packed
// f32x2 accumulators (A pair loaded directly as 64-bit from SMEM).
// ---------------------------------------------------------------------------
template<bool ADD_BIAS>
__global__ void __launch_bounds__(256, 2)
gemm_nt_kernel(const float* __restrict__ A, const float* __restrict__ B,
               const float* __restrict__ bias, float* __restrict__ C,
               int ldc, int k_len)
{
    constexpr int BN = 16, BK = 16;
    __shared__ float As[BK][128 + 4];
    __shared__ float Bs[BK][BN + 4];
    const int tid = threadIdx.x;
    const int tx = tid & 7;     // 8 col-groups of 2
    const int ty = tid >> 3;    // 32 row-groups of 4
    const int nbase = blockIdx.x * BN;
    const int k_lo = blockIdx.y * k_len;
    float* __restrict__ Cout = C + (size_t)blockIdx.y * 128u * (size_t)ldc;

    unsigned long long acc[2][2] = {{0ull, 0ull}, {0ull, 0ull}};

    float4 aR[2];
    float4 bR = make_float4(0.f, 0.f, 0.f, 0.f);

    // prefetch first tiles into registers
    #pragma unroll
    for (int i = 0; i < 2; i++) {
        int f = tid + i * 256;
        int r = f >> 2, kv = (f & 3) << 2;
        aR[i] = *(const float4*)&A[(size_t)r * KDIM + k_lo + kv];
    }
    if (tid < 64) {
        int r = tid >> 2, kv = (tid & 3) << 2;
        bR = *(const float4*)&B[(size_t)(nbase + r) * KDIM + k_lo + kv];
    }

    const int nIter = k_len / BK;
    for (int it = 0; it < nIter; it++) {
        // commit prefetched tiles to SMEM (transposed: As[k][m], Bs[k][n])
        #pragma unroll
        for (int i = 0; i < 2; i++) {
            int f = tid + i * 256;
            int r = f >> 2, kv = (f & 3) << 2;
            As[kv + 0][r] = aR[i].x; As[kv + 1][r] = aR[i].y;
            As[kv + 2][r] = aR[i].z; As[kv + 3][r] = aR[i].w;
        }
        if (tid < 64) {
            int r = tid >> 2, kv = (tid & 3) << 2;
            Bs[kv + 0][r] = bR.x; Bs[kv + 1][r] = bR.y;
            Bs[kv + 2][r] = bR.z; Bs[kv + 3][r] = bR.w;
        }
        __syncthreads();
        // prefetch next tile while computing this one
        if (it + 1 < nIter) {
            int k0 = k_lo + (it + 1) * BK;
            #pragma unroll
            for (int i = 0; i < 2; i++) {
                int f = tid + i * 256;
                int r = f >> 2, kv = (f & 3) << 2;
                aR[i] = *(const float4*)&A[(size_t)r * KDIM + k0 + kv];
            }
            if (tid < 64) {
                int r = tid >> 2, kv = (tid & 3) << 2;
                bR = *(const float4*)&B[(size_t)(nbase + r) * KDIM + k0 + kv];
            }
        }
        #pragma unroll
        for (int k = 0; k < BK; k++) {
            // A row-pairs come out of SMEM already packed as 64-bit values
            ulonglong2 av = *(const ulonglong2*)&As[k][ty * 4];
            float2 bv = *(const float2*)&Bs[k][tx * 2];
            unsigned long long bb0 = pack2(bv.x, bv.x);
            unsigned long long bb1 = pack2(bv.y, bv.y);
            ffma2(acc[0][0], av.x, bb0);
            ffma2(acc[0][1], av.x, bb1);
            ffma2(acc[1][0], av.y, bb0);
            ffma2(acc[1][1], av.y, bb1);
        }
        __syncthreads();
    }

    const int n = nbase + tx * 2;
    float bn0 = 0.f, bn1 = 0.f;
    if (ADD_BIAS) { bn0 = bias[n]; bn1 = bias[n + 1]; }
    #pragma unroll
    for (int r = 0; r < 2; r++) {
        float2 c0 = unpack2(acc[r][0]);   // (row m0, row m0+1) at col n
        float2 c1 = unpack2(acc[r][1]);   // (row m0, row m0+1) at col n+1
        int m0 = ty * 4 + r * 2;
        *(float2*)&Cout[(size_t)m0 * ldc + n]       = make_float2(c0.x + bn0, c1.x + bn1);
        *(float2*)&Cout[(size_t)(m0 + 1) * ldc + n] = make_float2(c0.y + bn0, c1.y + bn1);
    }
}

// Deterministic reduction of the 8 K-split partials + bias -> g_emb
__global__ void reduce2_kernel(const float* __restrict__ b_e) {
    int idx = blockIdx.x * blockDim.x + threadIdx.x;   // < 128*512
    float s = b_e[idx & (EMB - 1)];
    #pragma unroll
    for (int k = 0; k < 8; k++) s += g_part[(size_t)k * (B_SZ * EMB) + idx];
    g_emb[idx] = s;
}

// out[b,0] = -||relu(p_lfs[b] - emb[b])||  (one warp per b)
__global__ void pscore_kernel(const float* __restrict__ p_lfs, float* __restrict__ out) {
    int warp = threadIdx.x >> 5, lane = threadIdx.x & 31;
    int b = blockIdx.x * 8 + warp;
    const float* pp = p_lfs + (size_t)b * EMB;
    const float* ee = g_emb + (size_t)b * EMB;
    float s = 0.f;
    #pragma unroll
    for (int j = 0; j < 4; j++) {
        int d = j * 128 + lane * 4;
        float4 p = *(const float4*)&pp[d];
        float4 e = *(const float4*)&ee[d];
        float r0 = fmaxf(p.x - e.x, 0.f), r1 = fmaxf(p.y - e.y, 0.f);
        float r2 = fmaxf(p.z - e.z, 0.f), r3 = fmaxf(p.w - e.w, 0.f);
        s = fmaf(r0, r0, s); s = fmaf(r1, r1, s);
        s = fmaf(r2, r2, s); s = fmaf(r3, r3, s);
    }
    #pragma unroll
    for (int off = 16; off > 0; off >>= 1) s += __shfl_down_sync(0xffffffffu, s, off);
    if (lane == 0) out[(size_t)b * OUTW] = -sqrtf(s);
}

// out[b, 1+n] = -||relu(n_lfs[n] - emb[b])||
// GEMM-style tiling: block tile = 16 b x 128 n, per-thread 2b x 4n register
// accumulators, d streamed through SMEM in chunks of 32 (no shuffle reduces).
__global__ void __launch_bounds__(256, 2)
nscore_kernel(const float* __restrict__ n_lfs, float* __restrict__ out) {
    __shared__ float Ns[32][128 + 4];
    __shared__ float Es[16][32];
    const int tid = threadIdx.x;
    const int tx = tid & 31;          // n sub-tile: 4 n's each
    const int bq = tid >> 5;          // b sub-tile: warp -> b-pair (2*bq, 2*bq+1)
    const int nbase = blockIdx.x * 128;
    const int btile = blockIdx.y * 16;

    float acc[2][4] = {};
    float4 nR[4];
    float4 eR = make_float4(0.f, 0.f, 0.f, 0.f);

    // prefetch d-chunk 0
    #pragma unroll
    for (int i = 0; i < 4; i++) {
        int f = tid + i * 256;
        int row = f >> 3, dv = (f & 7) << 2;
        nR[i] = *(const float4*)&n_lfs[(size_t)(nbase + row) * EMB + dv];
    }
    if (tid < 128) {
        int row = tid >> 3, dv = (tid & 7) << 2;
        eR = *(const float4*)&g_emb[(size_t)(btile + row) * EMB + dv];
    }

    for (int it = 0; it < 16; it++) {
        #pragma unroll
        for (int i = 0; i < 4; i++) {
            int f = tid + i * 256;
            int row = f >> 3, dv = (f & 7) << 2;
            Ns[dv + 0][row] = nR[i].x; Ns[dv + 1][row] = nR[i].y;
            Ns[dv + 2][row] = nR[i].z; Ns[dv + 3][row] = nR[i].w;
        }
        if (tid < 128) {
            int row = tid >> 3, dv = (tid & 7) << 2;
            *(float4*)&Es[row][dv] = eR;
        }
        __syncthreads();
        if (it + 1 < 16) {
            int dc = (it + 1) * 32;
            #pragma unroll
            for (int i = 0; i < 4; i++) {
                int f = tid + i * 256;
                int row = f >> 3, dv = (f & 7) << 2;
                nR[i] = *(const float4*)&n_lfs[(size_t)(nbase + row) * EMB + dc + dv];
            }
            if (tid < 128) {
                int row = tid >> 3, dv = (tid & 7) << 2;
                eR = *(const float4*)&g_emb[(size_t)(btile + row) * EMB + dc + dv];
            }
        }
        #pragma unroll 8
        for (int d = 0; d < 32; d++) {
            float e0 = Es[bq * 2 + 0][d];    // warp-uniform -> SMEM broadcast
            float e1 = Es[bq * 2 + 1][d];
            float4 nv = *(const float4*)&Ns[d][tx * 4];
            float r;
            r = fmaxf(nv.x - e0, 0.f); acc[0][0] = fmaf(r, r, acc[0][0]);
            r = fmaxf(nv.y - e0, 0.f); acc[0][1] = fmaf(r, r, acc[0][1]);
            r = fmaxf(nv.z - e0, 0.f); acc[0][2] = fmaf(r, r, acc[0][2]);
            r = fmaxf(nv.w - e0, 0.f); acc[0][3] = fmaf(r, r, acc[0][3]);
            r = fmaxf(nv.x - e1, 0.f); acc[1][0] = fmaf(r, r, acc[1][0]);
            r = fmaxf(nv.y - e1, 0.f); acc[1][1] = fmaf(r, r, acc[1][1]);
            r = fmaxf(nv.z - e1, 0.f); acc[1][2] = fmaf(r, r, acc[1][2]);
            r = fmaxf(nv.w - e1, 0.f); acc[1][3] = fmaf(r, r, acc[1][3]);
        }
        __syncthreads();
    }

    #pragma unroll
    for (int bi = 0; bi < 2; bi++) {
        int b = btile + bq * 2 + bi;
        #pragma unroll
        for (int j = 0; j < 4; j++) {
            int n = nbase + tx * 4 + j;
            out[(size_t)b * OUTW + 1 + n] = -sqrtf(acc[bi][j]);
        }
    }
}

extern "C" void kernel_launch(void* const* d_in, const int* in_sizes, int n_in,
                              void* d_out, int out_size) {
    const float* vfs   = (const float*)d_in[0];
    const float* p_lfs = (const float*)d_in[1];
    const float* n_lfs = (const float*)d_in[2];
    const float* W_h   = (const float*)d_in[3];
    const float* b_h   = (const float*)d_in[4];
    const float* W_e   = (const float*)d_in[5];
    const float* b_e   = (const float*)d_in[6];
    float* out = (float*)d_out;

    float* hidden = nullptr;
    float* part = nullptr;
    cudaGetSymbolAddress((void**)&hidden, g_hidden);
    cudaGetSymbolAddress((void**)&part, g_part);

    // GEMM1: hidden = vfs @ W_h^T + b_h   (256 blocks, one wave at occ=2)
    gemm_nt_kernel<true ><<<dim3(KDIM / 16, 1), 256>>>(vfs, W_h, b_h, hidden, KDIM, KDIM);
    // GEMM2 (K-split x8): partials of hidden @ W_e^T
    gemm_nt_kernel<false><<<dim3(EMB / 16, 8), 256>>>(hidden, W_e, nullptr, part, EMB, KDIM / 8);
    // emb = sum partials + b_e
    reduce2_kernel<<<(B_SZ * EMB) / 256, 256>>>(b_e);
    // scores
    pscore_kernel<<<B_SZ / 8, 256>>>(p_lfs, out);
    nscore_kernel<<<dim3(NNEG / 128, B_SZ / 16), 256>>>(n_lfs, out);
}

// round 2
// speedup vs baseline: 1.8365x; 1.8365x over previous
#include <cuda_runtime.h>
#include <math.h>

#define B_SZ   128
#define KDIM   4096
#define EMB    512
#define NNEG   2048
#define OUTW   (NNEG + 1)

// Scratch (static device globals — no allocation).
// g_part is reused: GEMM1 partials (4*128*4096) then GEMM2 partials (32*128*512).
__device__ float g_part[2 * 1024 * 1024];    // 8 MB
__device__ float g_hidden[B_SZ * KDIM];      // 2 MB
__device__ float g_emb[B_SZ * EMB];          // 256 KB

// ---------------- packed f32x2 helpers (Blackwell FFMA2 path) ----------------
__device__ __forceinline__ unsigned long long pack2(float lo, float hi) {
    unsigned long long r;
    asm("mov.b64 %0, {%1, %2};" : "=l"(r) : "f"(lo), "f"(hi));
    return r;
}
__device__ __forceinline__ float2 unpack2(unsigned long long v) {
    float2 u;
    asm("mov.b64 {%0, %1}, %2;" : "=f"(u.x), "=f"(u.y) : "l"(v));
    return u;
}
__device__ __forceinline__ void ffma2(unsigned long long& d, unsigned long long a, unsigned long long b) {
    asm("fma.rn.f32x2 %0, %1, %2, %3;" : "=l"(d) : "l"(a), "l"(b), "l"(d));
}

// ---------------------------------------------------------------------------
// Split-K SGEMM: Cpart[sk][128, N] = A[128, k_lo:k_lo+k_len] @ B[:, ...]^T
// A [128, KDIM] row-major, B [N, KDIM] row-major (PyTorch W layout).
// BM=128, BN=128, BK=16, 256 threads, thread tile 8m x 8n, f32x2 accumulators
// packed along m-pairs (A pairs come out of SMEM pre-packed as 64-bit).
// ---------------------------------------------------------------------------
__global__ void __launch_bounds__(256, 1)
sgemm_nt(const float* __restrict__ A, const float* __restrict__ B,
         float* __restrict__ C, int ldc, int k_len)
{
    __shared__ float As[16][128 + 4];
    __shared__ float Bs[16][128 + 4];
    const int tid = threadIdx.x;
    const int tx = tid & 15;            // n-group (8 cols)
    const int ty = tid >> 4;            // m-group (8 rows)
    const int nbase = blockIdx.x * 128;
    const int k_lo = blockIdx.y * k_len;
    float* __restrict__ Cout = C + (size_t)blockIdx.y * 128u * (size_t)ldc;

    unsigned long long acc[4][8];
    #pragma unroll
    for (int i = 0; i < 4; i++)
        #pragma unroll
        for (int j = 0; j < 8; j++) acc[i][j] = 0ull;

    float4 aR[2], bR[2];
    // prefetch tile 0
    #pragma unroll
    for (int i = 0; i < 2; i++) {
        int idx = tid + i * 256;
        int r = idx >> 2, kv = (idx & 3) << 2;
        aR[i] = *(const float4*)&A[(size_t)r * KDIM + k_lo + kv];
        bR[i] = *(const float4*)&B[(size_t)(nbase + r) * KDIM + k_lo + kv];
    }

    const int nIter = k_len >> 4;
    for (int it = 0; it < nIter; it++) {
        // commit prefetched tiles (transposed: [k][m] / [k][n])
        #pragma unroll
        for (int i = 0; i < 2; i++) {
            int idx = tid + i * 256;
            int r = idx >> 2, kv = (idx & 3) << 2;
            As[kv + 0][r] = aR[i].x; As[kv + 1][r] = aR[i].y;
            As[kv + 2][r] = aR[i].z; As[kv + 3][r] = aR[i].w;
            Bs[kv + 0][r] = bR[i].x; Bs[kv + 1][r] = bR[i].y;
            Bs[kv + 2][r] = bR[i].z; Bs[kv + 3][r] = bR[i].w;
        }
        __syncthreads();
        if (it + 1 < nIter) {
            int k0 = k_lo + (it + 1) * 16;
            #pragma unroll
            for (int i = 0; i < 2; i++) {
                int idx = tid + i * 256;
                int r = idx >> 2, kv = (idx & 3) << 2;
                aR[i] = *(const float4*)&A[(size_t)r * KDIM + k0 + kv];
                bR[i] = *(const float4*)&B[(size_t)(nbase + r) * KDIM + k0 + kv];
            }
        }
        #pragma unroll
        for (int k = 0; k < 16; k++) {
            // 4 m-pairs, already packed in SMEM
            ulonglong2 a01 = *(const ulonglong2*)&As[k][ty * 8];
            ulonglong2 a23 = *(const ulonglong2*)&As[k][ty * 8 + 4];
            float4 b0 = *(const float4*)&Bs[k][tx * 8];
            float4 b1 = *(const float4*)&Bs[k][tx * 8 + 4];
            unsigned long long bb[8];
            bb[0] = pack2(b0.x, b0.x); bb[1] = pack2(b0.y, b0.y);
            bb[2] = pack2(b0.z, b0.z); bb[3] = pack2(b0.w, b0.w);
            bb[4] = pack2(b1.x, b1.x); bb[5] = pack2(b1.y, b1.y);
            bb[6] = pack2(b1.z, b1.z); bb[7] = pack2(b1.w, b1.w);
            #pragma unroll
            for (int n = 0; n < 8; n++) {
                ffma2(acc[0][n], a01.x, bb[n]);
                ffma2(acc[1][n], a01.y, bb[n]);
                ffma2(acc[2][n], a23.x, bb[n]);
                ffma2(acc[3][n], a23.y, bb[n]);
            }
        }
        __syncthreads();
    }

    // epilogue: 8x8 tile -> 16 float4 stores
    #pragma unroll
    for (int mp = 0; mp < 4; mp++) {
        int m0 = ty * 8 + mp * 2;
        #pragma unroll
        for (int g = 0; g < 2; g++) {
            float2 u0 = unpack2(acc[mp][g * 4 + 0]);
            float2 u1 = unpack2(acc[mp][g * 4 + 1]);
            float2 u2 = unpack2(acc[mp][g * 4 + 2]);
            float2 u3 = unpack2(acc[mp][g * 4 + 3]);
            int n = nbase + tx * 8 + g * 4;
            *(float4*)&Cout[(size_t)m0 * ldc + n]       = make_float4(u0.x, u1.x, u2.x, u3.x);
            *(float4*)&Cout[(size_t)(m0 + 1) * ldc + n] = make_float4(u0.y, u1.y, u2.y, u3.y);
        }
    }
}

// hidden = sum_{sk<4} part[sk] + b_h
__global__ void reduce_hidden(const float* __restrict__ b_h) {
    int idx = blockIdx.x * blockDim.x + threadIdx.x;   // < 128*4096
    float s = b_h[idx & (KDIM - 1)];
    #pragma unroll
    for (int k = 0; k < 4; k++) s += g_part[(size_t)k * (B_SZ * KDIM) + idx];
    g_hidden[idx] = s;
}

// emb = sum_{sk<32} part[sk] + b_e
__global__ void reduce_emb(const float* __restrict__ b_e) {
    int idx = blockIdx.x * blockDim.x + threadIdx.x;   // < 128*512
    float s = b_e[idx & (EMB - 1)];
    #pragma unroll
    for (int k = 0; k < 32; k++) s += g_part[(size_t)k * (B_SZ * EMB) + idx];
    g_emb[idx] = s;
}

// out[b,0] = -||relu(p_lfs[b] - emb[b])||  (one warp per b)
__global__ void pscore_kernel(const float* __restrict__ p_lfs, float* __restrict__ out) {
    int warp = threadIdx.x >> 5, lane = threadIdx.x & 31;
    int b = blockIdx.x * 8 + warp;
    const float* pp = p_lfs + (size_t)b * EMB;
    const float* ee = g_emb + (size_t)b * EMB;
    float s = 0.f;
    #pragma unroll
    for (int j = 0; j < 4; j++) {
        int d = j * 128 + lane * 4;
        float4 p = *(const float4*)&pp[d];
        float4 e = *(const float4*)&ee[d];
        float r0 = fmaxf(p.x - e.x, 0.f), r1 = fmaxf(p.y - e.y, 0.f);
        float r2 = fmaxf(p.z - e.z, 0.f), r3 = fmaxf(p.w - e.w, 0.f);
        s = fmaf(r0, r0, s); s = fmaf(r1, r1, s);
        s = fmaf(r2, r2, s); s = fmaf(r3, r3, s);
    }
    #pragma unroll
    for (int off = 16; off > 0; off >>= 1) s += __shfl_down_sync(0xffffffffu, s, off);
    if (lane == 0) out[(size_t)b * OUTW] = -sqrtf(s);
}

// out[b, 1+n] = -||relu(n_lfs[n] - emb[b])||
// block tile = 16 b x 128 n, per-thread 2b x 4n accumulators, d chunks of 32.
__global__ void __launch_bounds__(256, 2)
nscore_kernel(const float* __restrict__ n_lfs, float* __restrict__ out) {
    __shared__ float Ns[32][128 + 4];
    __shared__ float Es[16][32];
    const int tid = threadIdx.x;
    const int tx = tid & 31;
    const int bq = tid >> 5;
    const int nbase = blockIdx.x * 128;
    const int btile = blockIdx.y * 16;

    float acc[2][4] = {};
    float4 nR[4];
    float4 eR = make_float4(0.f, 0.f, 0.f, 0.f);

    #pragma unroll
    for (int i = 0; i < 4; i++) {
        int f = tid + i * 256;
        int row = f >> 3, dv = (f & 7) << 2;
        nR[i] = *(const float4*)&n_lfs[(size_t)(nbase + row) * EMB + dv];
    }
    if (tid < 128) {
        int row = tid >> 3, dv = (tid & 7) << 2;
        eR = *(const float4*)&g_emb[(size_t)(btile + row) * EMB + dv];
    }

    for (int it = 0; it < 16; it++) {
        #pragma unroll
        for (int i = 0; i < 4; i++) {
            int f = tid + i * 256;
            int row = f >> 3, dv = (f & 7) << 2;
            Ns[dv + 0][row] = nR[i].x; Ns[dv + 1][row] = nR[i].y;
            Ns[dv + 2][row] = nR[i].z; Ns[dv + 3][row] = nR[i].w;
        }
        if (tid < 128) {
            int row = tid >> 3, dv = (tid & 7) << 2;
            *(float4*)&Es[row][dv] = eR;
        }
        __syncthreads();
        if (it + 1 < 16) {
            int dc = (it + 1) * 32;
            #pragma unroll
            for (int i = 0; i < 4; i++) {
                int f = tid + i * 256;
                int row = f >> 3, dv = (f & 7) << 2;
                nR[i] = *(const float4*)&n_lfs[(size_t)(nbase + row) * EMB + dc + dv];
            }
            if (tid < 128) {
                int row = tid >> 3, dv = (tid & 7) << 2;
                eR = *(const float4*)&g_emb[(size_t)(btile + row) * EMB + dc + dv];
            }
        }
        #pragma unroll 8
        for (int d = 0; d < 32; d++) {
            float e0 = Es[bq * 2 + 0][d];
            float e1 = Es[bq * 2 + 1][d];
            float4 nv = *(const float4*)&Ns[d][tx * 4];
            float r;
            r = fmaxf(nv.x - e0, 0.f); acc[0][0] = fmaf(r, r, acc[0][0]);
            r = fmaxf(nv.y - e0, 0.f); acc[0][1] = fmaf(r, r, acc[0][1]);
            r = fmaxf(nv.z - e0, 0.f); acc[0][2] = fmaf(r, r, acc[0][2]);
            r = fmaxf(nv.w - e0, 0.f); acc[0][3] = fmaf(r, r, acc[0][3]);
            r = fmaxf(nv.x - e1, 0.f); acc[1][0] = fmaf(r, r, acc[1][0]);
            r = fmaxf(nv.y - e1, 0.f); acc[1][1] = fmaf(r, r, acc[1][1]);
            r = fmaxf(nv.z - e1, 0.f); acc[1][2] = fmaf(r, r, acc[1][2]);
            r = fmaxf(nv.w - e1, 0.f); acc[1][3] = fmaf(r, r, acc[1][3]);
        }
        __syncthreads();
    }

    #pragma unroll
    for (int bi = 0; bi < 2; bi++) {
        int b = btile + bq * 2 + bi;
        #pragma unroll
        for (int j = 0; j < 4; j++) {
            int n = nbase + tx * 4 + j;
            out[(size_t)b * OUTW + 1 + n] = -sqrtf(acc[bi][j]);
        }
    }
}

extern "C" void kernel_launch(void* const* d_in, const int* in_sizes, int n_in,
                              void* d_out, int out_size) {
    const float* vfs   = (const float*)d_in[0];
    const float* p_lfs = (const float*)d_in[1];
    const float* n_lfs = (const float*)d_in[2];
    const float* W_h   = (const float*)d_in[3];
    const float* b_h   = (const float*)d_in[4];
    const float* W_e   = (const float*)d_in[5];
    const float* b_e   = (const float*)d_in[6];
    float* out = (float*)d_out;

    float* part = nullptr;
    float* hidden = nullptr;
    cudaGetSymbolAddress((void**)&part, g_part);
    cudaGetSymbolAddress((void**)&hidden, g_hidden);

    // GEMM1: part[4][128][4096] = vfs @ W_h^T (K-split 4 -> 128 blocks)
    sgemm_nt<<<dim3(KDIM / 128, 4), 256>>>(vfs, W_h, part, KDIM, KDIM / 4);
    reduce_hidden<<<(B_SZ * KDIM) / 256, 256>>>(b_h);
    // GEMM2: part[32][128][512] = hidden @ W_e^T (K-split 32 -> 128 blocks)
    sgemm_nt<<<dim3(EMB / 128, 32), 256>>>(hidden, W_e, part, EMB, KDIM / 32);
    reduce_emb<<<(B_SZ * EMB) / 256, 256>>>(b_e);
    // scores
    pscore_kernel<<<B_SZ / 8, 256>>>(p_lfs, out);
    nscore_kernel<<<dim3(NNEG / 128, B_SZ / 16), 256>>>(n_lfs, out);
}

// round 4
// speedup vs baseline: 2.1223x; 1.1556x over previous
#include <cuda_runtime.h>
#include <mma.h>
#include <math.h>
#include <cstdint>

using namespace nvcuda;

#define B_SZ   128
#define KDIM   4096
#define EMB    512
#define NNEG   2048
#define OUTW   (NNEG + 1)

// Scratch (static device globals — no allocation).
__device__ float g_part[2 * 1024 * 1024];    // 8 MB (split-K partials, reused)
__device__ float g_hidden[B_SZ * KDIM];      // 2 MB
__device__ float g_emb[B_SZ * EMB];          // 256 KB

__device__ __forceinline__ float f2tf32f(float x) {
    uint32_t r; asm("cvt.rna.tf32.f32 %0, %1;" : "=r"(r) : "f"(x));
    return __uint_as_float(r);
}

// ---------------------------------------------------------------------------
// tf32 WMMA split-K GEMM: Cpart[sk][128, N] = A[128, ksl] @ B[N, ksl]^T
// A [128, KDIM] f32 row-major, B [N, KDIM] f32 row-major (PyTorch W layout).
// BM=128, BN=128, BK=32, 256 threads (8 warps, 2x4), warp tile 64x32,
// double-buffered SMEM staged through cvt.rna.tf32.
// SMEM layout per buffer: A[128][36], B[128][36] (ld=36 floats, 16B-aligned rows)
// ---------------------------------------------------------------------------
#define LDS_SM 36

__device__ __forceinline__ void stage_tile(float* __restrict__ sA, float* __restrict__ sB,
    const float* __restrict__ A, const float* __restrict__ B,
    int k0, int tid, int nbase)
{
    #pragma unroll
    for (int i = 0; i < 2; i++) {
        int idx = tid + i * 256;          // 0..511 -> 128 rows x 4 col-groups
        int row = idx >> 2;
        int c = (idx & 3) << 3;           // col group of 8 floats
        const float* pa = &A[(size_t)row * KDIM + k0 + c];
        const float* pb = &B[(size_t)(nbase + row) * KDIM + k0 + c];
        float4 a0 = *(const float4*)pa;
        float4 a1 = *(const float4*)(pa + 4);
        float4 b0 = *(const float4*)pb;
        float4 b1 = *(const float4*)(pb + 4);
        float* da = &sA[row * LDS_SM + c];
        float* db = &sB[row * LDS_SM + c];
        da[0] = f2tf32f(a0.x); da[1] = f2tf32f(a0.y); da[2] = f2tf32f(a0.z); da[3] = f2tf32f(a0.w);
        da[4] = f2tf32f(a1.x); da[5] = f2tf32f(a1.y); da[6] = f2tf32f(a1.z); da[7] = f2tf32f(a1.w);
        db[0] = f2tf32f(b0.x); db[1] = f2tf32f(b0.y); db[2] = f2tf32f(b0.z); db[3] = f2tf32f(b0.w);
        db[4] = f2tf32f(b1.x); db[5] = f2tf32f(b1.y); db[6] = f2tf32f(b1.z); db[7] = f2tf32f(b1.w);
    }
}

__global__ void __launch_bounds__(256, 1)
wmma_gemm(const float* __restrict__ A, const float* __restrict__ B,
          float* __restrict__ C, int ldc, int k_len)
{
    extern __shared__ float smem[];
    float* sA[2] = { smem,                  smem + 2 * 128 * LDS_SM };
    float* sB[2] = { smem + 128 * LDS_SM,   smem + 3 * 128 * LDS_SM };

    const int tid = threadIdx.x;
    const int wid = tid >> 5;
    const int wm = wid >> 2;            // 0..1 -> m offset 64*wm
    const int wn = wid & 3;             // 0..3 -> n offset 32*wn
    const int nbase = blockIdx.x * 128;
    const int k_lo = blockIdx.y * k_len;
    float* __restrict__ Cout = C + (size_t)blockIdx.y * 128u * (size_t)ldc;

    wmma::fragment<wmma::accumulator, 16, 16, 8, float> acc[4][2];
    #pragma unroll
    for (int i = 0; i < 4; i++)
        #pragma unroll
        for (int j = 0; j < 2; j++) wmma::fill_fragment(acc[i][j], 0.0f);

    stage_tile(sA[0], sB[0], A, B, k_lo, tid, nbase);
    __syncthreads();

    const int nIter = k_len >> 5;
    for (int it = 0; it < nIter; it++) {
        int p = it & 1;
        // prefetch next tile into the other buffer (no sync needed before
        // writing buffer q: it was consumed two iterations ago, and the
        // __syncthreads at the end of the previous iteration covers it)
        if (it + 1 < nIter)
            stage_tile(sA[p ^ 1], sB[p ^ 1], A, B, k_lo + (it + 1) * 32, tid, nbase);

        #pragma unroll
        for (int ks = 0; ks < 4; ks++) {
            int k0 = ks * 8;
            wmma::fragment<wmma::matrix_a, 16, 16, 8, wmma::precision::tf32, wmma::row_major> af[4];
            wmma::fragment<wmma::matrix_b, 16, 16, 8, wmma::precision::tf32, wmma::col_major> bf[2];
            #pragma unroll
            for (int i = 0; i < 4; i++)
                wmma::load_matrix_sync(af[i], &sA[p][(wm * 64 + i * 16) * LDS_SM + k0], LDS_SM);
            #pragma unroll
            for (int j = 0; j < 2; j++)
                wmma::load_matrix_sync(bf[j], &sB[p][(wn * 32 + j * 16) * LDS_SM + k0], LDS_SM);
            #pragma unroll
            for (int i = 0; i < 4; i++)
                #pragma unroll
                for (int j = 0; j < 2; j++)
                    wmma::mma_sync(acc[i][j], af[i], bf[j], acc[i][j]);
        }
        __syncthreads();
    }

    #pragma unroll
    for (int i = 0; i < 4; i++)
        #pragma unroll
        for (int j = 0; j < 2; j++) {
            int m0 = wm * 64 + i * 16;
            int n0 = nbase + wn * 32 + j * 16;
            wmma::store_matrix_sync(&Cout[(size_t)m0 * ldc + n0], acc[i][j], ldc,
                                    wmma::mem_row_major);
        }
}

// hidden = sum_{sk<4} part[sk] + b_h
__global__ void reduce_hidden(const float* __restrict__ b_h) {
    int idx = blockIdx.x * blockDim.x + threadIdx.x;   // < 128*4096
    float s = b_h[idx & (KDIM - 1)];
    #pragma unroll
    for (int k = 0; k < 4; k++) s += g_part[(size_t)k * (B_SZ * KDIM) + idx];
    g_hidden[idx] = s;
}

// emb = sum_{sk<16} part[sk] + b_e
__global__ void reduce_emb(const float* __restrict__ b_e) {
    int idx = blockIdx.x * blockDim.x + threadIdx.x;   // < 128*512
    float s = b_e[idx & (EMB - 1)];
    #pragma unroll
    for (int k = 0; k < 16; k++) s += g_part[(size_t)k * (B_SZ * EMB) + idx];
    g_emb[idx] = s;
}

// out[b, 1+n] = -||relu(n_lfs[n] - emb[b])|| ; blocks with bx==16 do the
// positive scores out[b,0] = -||relu(p_lfs[b] - emb[b])|| instead.
__global__ void __launch_bounds__(256, 2)
nscore_kernel(const float* __restrict__ n_lfs, const float* __restrict__ p_lfs,
              float* __restrict__ out) {
    const int tid = threadIdx.x;
    const int btile = blockIdx.y * 16;

    if (blockIdx.x == 16) {   // positive-score path: 8 warps x 2 b each
        int wq = tid >> 5, lane = tid & 31;
        #pragma unroll
        for (int r = 0; r < 2; r++) {
            int b = btile + wq * 2 + r;
            const float* pp = p_lfs + (size_t)b * EMB;
            const float* ee = g_emb + (size_t)b * EMB;
            float s = 0.f;
            #pragma unroll
            for (int j = 0; j < 4; j++) {
                int d = j * 128 + lane * 4;
                float4 p = *(const float4*)&pp[d];
                float4 e = *(const float4*)&ee[d];
                float r0 = fmaxf(p.x - e.x, 0.f), r1 = fmaxf(p.y - e.y, 0.f);
                float r2 = fmaxf(p.z - e.z, 0.f), r3 = fmaxf(p.w - e.w, 0.f);
                s = fmaf(r0, r0, s); s = fmaf(r1, r1, s);
                s = fmaf(r2, r2, s); s = fmaf(r3, r3, s);
            }
            #pragma unroll
            for (int off = 16; off > 0; off >>= 1) s += __shfl_down_sync(0xffffffffu, s, off);
            if (lane == 0) out[(size_t)b * OUTW] = -sqrtf(s);
        }
        return;
    }

    __shared__ float Ns[32][128 + 4];
    __shared__ float Es[16][32];
    const int tx = tid & 31;
    const int bq = tid >> 5;
    const int nbase = blockIdx.x * 128;

    float acc[2][4] = {};
    float4 nR[4];
    float4 eR = make_float4(0.f, 0.f, 0.f, 0.f);

    #pragma unroll
    for (int i = 0; i < 4; i++) {
        int f = tid + i * 256;
        int row = f >> 3, dv = (f & 7) << 2;
        nR[i] = *(const float4*)&n_lfs[(size_t)(nbase + row) * EMB + dv];
    }
    if (tid < 128) {
        int row = tid >> 3, dv = (tid & 7) << 2;
        eR = *(const float4*)&g_emb[(size_t)(btile + row) * EMB + dv];
    }

    for (int it = 0; it < 16; it++) {
        #pragma unroll
        for (int i = 0; i < 4; i++) {
            int f = tid + i * 256;
            int row = f >> 3, dv = (f & 7) << 2;
            Ns[dv + 0][row] = nR[i].x; Ns[dv + 1][row] = nR[i].y;
            Ns[dv + 2][row] = nR[i].z; Ns[dv + 3][row] = nR[i].w;
        }
        if (tid < 128) {
            int row = tid >> 3, dv = (tid & 7) << 2;
            *(float4*)&Es[row][dv] = eR;
        }
        __syncthreads();
        if (it + 1 < 16) {
            int dc = (it + 1) * 32;
            #pragma unroll
            for (int i = 0; i < 4; i++) {
                int f = tid + i * 256;
                int row = f >> 3, dv = (f & 7) << 2;
                nR[i] = *(const float4*)&n_lfs[(size_t)(nbase + row) * EMB + dc + dv];
            }
            if (tid < 128) {
                int row = tid >> 3, dv = (tid & 7) << 2;
                eR = *(const float4*)&g_emb[(size_t)(btile + row) * EMB + dc + dv];
            }
        }
        #pragma unroll 8
        for (int d = 0; d < 32; d++) {
            float e0 = Es[bq * 2 + 0][d];
            float e1 = Es[bq * 2 + 1][d];
            float4 nv = *(const float4*)&Ns[d][tx * 4];
            float r;
            r = fmaxf(nv.x - e0, 0.f); acc[0][0] = fmaf(r, r, acc[0][0]);
            r = fmaxf(nv.y - e0, 0.f); acc[0][1] = fmaf(r, r, acc[0][1]);
            r = fmaxf(nv.z - e0, 0.f); acc[0][2] = fmaf(r, r, acc[0][2]);
            r = fmaxf(nv.w - e0, 0.f); acc[0][3] = fmaf(r, r, acc[0][3]);
            r = fmaxf(nv.x - e1, 0.f); acc[1][0] = fmaf(r, r, acc[1][0]);
            r = fmaxf(nv.y - e1, 0.f); acc[1][1] = fmaf(r, r, acc[1][1]);
            r = fmaxf(nv.z - e1, 0.f); acc[1][2] = fmaf(r, r, acc[1][2]);
            r = fmaxf(nv.w - e1, 0.f); acc[1][3] = fmaf(r, r, acc[1][3]);
        }
        __syncthreads();
    }

    #pragma unroll
    for (int bi = 0; bi < 2; bi++) {
        int b = btile + bq * 2 + bi;
        #pragma unroll
        for (int j = 0; j < 4; j++) {
            int n = nbase + tx * 4 + j;
            out[(size_t)b * OUTW + 1 + n] = -sqrtf(acc[bi][j]);
        }
    }
}

extern "C" void kernel_launch(void* const* d_in, const int* in_sizes, int n_in,
                              void* d_out, int out_size) {
    const float* vfs   = (const float*)d_in[0];
    const float* p_lfs = (const float*)d_in[1];
    const float* n_lfs = (const float*)d_in[2];
    const float* W_h   = (const float*)d_in[3];
    const float* b_h   = (const float*)d_in[4];
    const float* W_e   = (const float*)d_in[5];
    const float* b_e   = (const float*)d_in[6];
    float* out = (float*)d_out;

    float* part = nullptr;
    float* hidden = nullptr;
    cudaGetSymbolAddress((void**)&part, g_part);
    cudaGetSymbolAddress((void**)&hidden, g_hidden);

    const int SMEM_BYTES = 4 * 128 * LDS_SM * 4;   // 73728
    static bool attr_set = false;
    if (!attr_set) {
        cudaFuncSetAttribute(wmma_gemm, cudaFuncAttributeMaxDynamicSharedMemorySize, SMEM_BYTES);
        attr_set = true;
    }

    // GEMM1: part[4][128][4096] = vfs @ W_h^T  (tf32 WMMA, K-split 4 -> 128 CTAs)
    wmma_gemm<<<dim3(KDIM / 128, 4), 256, SMEM_BYTES>>>(vfs, W_h, part, KDIM, KDIM / 4);
    reduce_hidden<<<(B_SZ * KDIM) / 256, 256>>>(b_h);
    // GEMM2: part[16][128][512] = hidden @ W_e^T (K-split 16 -> 64 CTAs)
    wmma_gemm<<<dim3(EMB / 128, 16), 256, SMEM_BYTES>>>(hidden, W_e, part, EMB, KDIM / 16);
    reduce_emb<<<(B_SZ * EMB) / 256, 256>>>(b_e);
    // scores (bx==16 blocks do positive scores)
    nscore_kernel<<<dim3(NNEG / 128 + 1, B_SZ / 16), 256>>>(n_lfs, p_lfs, out);
}

// round 6
// speedup vs baseline: 2.6146x; 1.2320x over previous
#include <cuda_runtime.h>
#include <mma.h>
#include <math.h>
#include <cstdint>

using namespace nvcuda;

#define B_SZ   128
#define KDIM   4096
#define EMB    512
#define NNEG   2048
#define OUTW   (NNEG + 1)

#define STAGES 3
#define BK     32
#define LDS_SM 36    // padded row length in floats (144B, 16B-aligned)

// Scratch (static device globals — no allocation).
__device__ float g_part[2 * 1024 * 1024];    // 8 MB (split-K partials, reused)
__device__ float g_hidden[B_SZ * KDIM];      // 2 MB
__device__ float g_emb[B_SZ * EMB];          // 256 KB

__device__ __forceinline__ float f2tf32f(float x) {
    uint32_t r; asm("cvt.rna.tf32.f32 %0, %1;" : "=r"(r) : "f"(x));
    return __uint_as_float(r);
}
__device__ __forceinline__ uint32_t smem_u32(const void* p) {
    uint32_t a;
    asm("{ .reg .u64 t; cvta.to.shared.u64 t, %1; cvt.u32.u64 %0, t; }" : "=r"(a) : "l"(p));
    return a;
}

// ---------------------------------------------------------------------------
// tf32 WMMA split-K GEMM with cp.async 3-stage pipeline.
// Cpart[sk][128, N] = A[128, ksl] @ B[N, ksl]^T
// A [128, KDIM] f32 row-major, B [N, KDIM] f32 row-major (PyTorch W layout).
// BM=128, BN=128, BK=32, 256 threads (8 warps 2x4), warp tile 64x32.
// tf32 rounding applied in-register on fragments (rna), data staged raw f32.
// ---------------------------------------------------------------------------
__device__ __forceinline__ void issue_stage(float* smem, int s,
    const float* __restrict__ A, const float* __restrict__ B,
    int k0, int tid, int nbase, bool active)
{
    if (active) {
        float* sA = smem + s * (2 * 128 * LDS_SM);
        float* sB = sA + 128 * LDS_SM;
        #pragma unroll
        for (int i = 0; i < 4; i++) {
            int c = tid + i * 256;               // 0..1023 chunk id
            int row = c >> 3;
            int seg = (c & 7) << 2;              // float offset of 16B chunk
            const float* ga = &A[(size_t)row * KDIM + k0 + seg];
            const float* gb = &B[(size_t)(nbase + row) * KDIM + k0 + seg];
            uint32_t da = smem_u32(&sA[row * LDS_SM + seg]);
            uint32_t db = smem_u32(&sB[row * LDS_SM + seg]);
            asm volatile("cp.async.cg.shared.global [%0], [%1], 16;" :: "r"(da), "l"(ga) : "memory");
            asm volatile("cp.async.cg.shared.global [%0], [%1], 16;" :: "r"(db), "l"(gb) : "memory");
        }
    }
    asm volatile("cp.async.commit_group;" ::: "memory");
}

__global__ void __launch_bounds__(256, 1)
wmma_gemm(const float* __restrict__ A, const float* __restrict__ B,
          float* __restrict__ C, int ldc, int k_len)
{
    extern __shared__ float smem[];
    const int tid = threadIdx.x;
    const int wid = tid >> 5;
    const int wm = wid >> 2;            // m offset 64*wm
    const int wn = wid & 3;             // n offset 32*wn
    const int nbase = blockIdx.x * 128;
    const int k_lo = blockIdx.y * k_len;
    float* __restrict__ Cout = C + (size_t)blockIdx.y * 128u * (size_t)ldc;

    wmma::fragment<wmma::accumulator, 16, 16, 8, float> acc[4][2];
    #pragma unroll
    for (int i = 0; i < 4; i++)
        #pragma unroll
        for (int j = 0; j < 2; j++) wmma::fill_fragment(acc[i][j], 0.0f);

    const int nIter = k_len / BK;

    // prologue: issue STAGES-1 stages
    #pragma unroll
    for (int s = 0; s < STAGES - 1; s++)
        issue_stage(smem, s, A, B, k_lo + s * BK, tid, nbase, s < nIter);

    for (int it = 0; it < nIter; it++) {
        int ns = it + STAGES - 1;
        issue_stage(smem, ns % STAGES, A, B, k_lo + ns * BK, tid, nbase, ns < nIter);
        asm volatile("cp.async.wait_group %0;" :: "n"(STAGES - 1) : "memory");
        __syncthreads();

        float* sA = smem + (it % STAGES) * (2 * 128 * LDS_SM);
        float* sB = sA + 128 * LDS_SM;
        #pragma unroll
        for (int ks = 0; ks < BK / 8; ks++) {
            int k0 = ks * 8;
            wmma::fragment<wmma::matrix_a, 16, 16, 8, wmma::precision::tf32, wmma::row_major> af[4];
            wmma::fragment<wmma::matrix_b, 16, 16, 8, wmma::precision::tf32, wmma::col_major> bf[2];
            #pragma unroll
            for (int i = 0; i < 4; i++) {
                wmma::load_matrix_sync(af[i], &sA[(wm * 64 + i * 16) * LDS_SM + k0], LDS_SM);
                #pragma unroll
                for (int e = 0; e < af[i].num_elements; e++) af[i].x[e] = f2tf32f(af[i].x[e]);
            }
            #pragma unroll
            for (int j = 0; j < 2; j++) {
                wmma::load_matrix_sync(bf[j], &sB[(wn * 32 + j * 16) * LDS_SM + k0], LDS_SM);
                #pragma unroll
                for (int e = 0; e < bf[j].num_elements; e++) bf[j].x[e] = f2tf32f(bf[j].x[e]);
            }
            #pragma unroll
            for (int i = 0; i < 4; i++)
                #pragma unroll
                for (int j = 0; j < 2; j++)
                    wmma::mma_sync(acc[i][j], af[i], bf[j], acc[i][j]);
        }
        __syncthreads();
    }

    #pragma unroll
    for (int i = 0; i < 4; i++)
        #pragma unroll
        for (int j = 0; j < 2; j++) {
            int m0 = wm * 64 + i * 16;
            int n0 = nbase + wn * 32 + j * 16;
            wmma::store_matrix_sync(&Cout[(size_t)m0 * ldc + n0], acc[i][j], ldc,
                                    wmma::mem_row_major);
        }
}

// hidden = sum_{sk<4} part[sk] + b_h  (float4, 512 blocks)
__global__ void reduce_hidden(const float* __restrict__ b_h) {
    int i4 = blockIdx.x * blockDim.x + threadIdx.x;     // < 131072
    float4 s = ((const float4*)b_h)[i4 & (KDIM / 4 - 1)];
    #pragma unroll
    for (int k = 0; k < 4; k++) {
        float4 v = *(const float4*)&g_part[(size_t)k * (B_SZ * KDIM) + i4 * 4];
        s.x += v.x; s.y += v.y; s.z += v.z; s.w += v.w;
    }
    ((float4*)g_hidden)[i4] = s;
}

// emb = sum_{sk<16} part[sk] + b_e  (float4, 64 blocks)
__global__ void reduce_emb(const float* __restrict__ b_e) {
    int i4 = blockIdx.x * blockDim.x + threadIdx.x;     // < 16384
    float4 s = ((const float4*)b_e)[i4 & (EMB / 4 - 1)];
    #pragma unroll
    for (int k = 0; k < 16; k++) {
        float4 v = *(const float4*)&g_part[(size_t)k * (B_SZ * EMB) + i4 * 4];
        s.x += v.x; s.y += v.y; s.z += v.z; s.w += v.w;
    }
    ((float4*)g_emb)[i4] = s;
}

// out[b, 1+n] = -||relu(n_lfs[n] - emb[b])|| ; blocks with bx==16 do the
// positive scores out[b,0] = -||relu(p_lfs[b] - emb[b])|| instead.
__global__ void __launch_bounds__(256, 2)
nscore_kernel(const float* __restrict__ n_lfs, const float* __restrict__ p_lfs,
              float* __restrict__ out) {
    const int tid = threadIdx.x;
    const int btile = blockIdx.y * 16;

    if (blockIdx.x == 16) {   // positive-score path: 8 warps x 2 b each
        int wq = tid >> 5, lane = tid & 31;
        #pragma unroll
        for (int r = 0; r < 2; r++) {
            int b = btile + wq * 2 + r;
            const float* pp = p_lfs + (size_t)b * EMB;
            const float* ee = g_emb + (size_t)b * EMB;
            float s = 0.f;
            #pragma unroll
            for (int j = 0; j < 4; j++) {
                int d = j * 128 + lane * 4;
                float4 p = *(const float4*)&pp[d];
                float4 e = *(const float4*)&ee[d];
                float r0 = fmaxf(p.x - e.x, 0.f), r1 = fmaxf(p.y - e.y, 0.f);
                float r2 = fmaxf(p.z - e.z, 0.f), r3 = fmaxf(p.w - e.w, 0.f);
                s = fmaf(r0, r0, s); s = fmaf(r1, r1, s);
                s = fmaf(r2, r2, s); s = fmaf(r3, r3, s);
            }
            #pragma unroll
            for (int off = 16; off > 0; off >>= 1) s += __shfl_down_sync(0xffffffffu, s, off);
            if (lane == 0) out[(size_t)b * OUTW] = -sqrtf(s);
        }
        return;
    }

    __shared__ float Ns[32][128 + 4];
    __shared__ float Es[16][32];
    const int tx = tid & 31;
    const int bq = tid >> 5;
    const int nbase = blockIdx.x * 128;

    float acc[2][4] = {};
    float4 nR[4];
    float4 eR = make_float4(0.f, 0.f, 0.f, 0.f);

    #pragma unroll
    for (int i = 0; i < 4; i++) {
        int f = tid + i * 256;
        int row = f >> 3, dv = (f & 7) << 2;
        nR[i] = *(const float4*)&n_lfs[(size_t)(nbase + row) * EMB + dv];
    }
    if (tid < 128) {
        int row = tid >> 3, dv = (tid & 7) << 2;
        eR = *(const float4*)&g_emb[(size_t)(btile + row) * EMB + dv];
    }

    for (int it = 0; it < 16; it++) {
        #pragma unroll
        for (int i = 0; i < 4; i++) {
            int f = tid + i * 256;
            int row = f >> 3, dv = (f & 7) << 2;
            Ns[dv + 0][row] = nR[i].x; Ns[dv + 1][row] = nR[i].y;
            Ns[dv + 2][row] = nR[i].z; Ns[dv + 3][row] = nR[i].w;
        }
        if (tid < 128) {
            int row = tid >> 3, dv = (tid & 7) << 2;
            *(float4*)&Es[row][dv] = eR;
        }
        __syncthreads();
        if (it + 1 < 16) {
            int dc = (it + 1) * 32;
            #pragma unroll
            for (int i = 0; i < 4; i++) {
                int f = tid + i * 256;
                int row = f >> 3, dv = (f & 7) << 2;
                nR[i] = *(const float4*)&n_lfs[(size_t)(nbase + row) * EMB + dc + dv];
            }
            if (tid < 128) {
                int row = tid >> 3, dv = (tid & 7) << 2;
                eR = *(const float4*)&g_emb[(size_t)(btile + row) * EMB + dc + dv];
            }
        }
        #pragma unroll 8
        for (int d = 0; d < 32; d++) {
            float e0 = Es[bq * 2 + 0][d];
            float e1 = Es[bq * 2 + 1][d];
            float4 nv = *(const float4*)&Ns[d][tx * 4];
            float r;
            r = fmaxf(nv.x - e0, 0.f); acc[0][0] = fmaf(r, r, acc[0][0]);
            r = fmaxf(nv.y - e0, 0.f); acc[0][1] = fmaf(r, r, acc[0][1]);
            r = fmaxf(nv.z - e0, 0.f); acc[0][2] = fmaf(r, r, acc[0][2]);
            r = fmaxf(nv.w - e0, 0.f); acc[0][3] = fmaf(r, r, acc[0][3]);
            r = fmaxf(nv.x - e1, 0.f); acc[1][0] = fmaf(r, r, acc[1][0]);
            r = fmaxf(nv.y - e1, 0.f); acc[1][1] = fmaf(r, r, acc[1][1]);
            r = fmaxf(nv.z - e1, 0.f); acc[1][2] = fmaf(r, r, acc[1][2]);
            r = fmaxf(nv.w - e1, 0.f); acc[1][3] = fmaf(r, r, acc[1][3]);
        }
        __syncthreads();
    }

    #pragma unroll
    for (int bi = 0; bi < 2; bi++) {
        int b = btile + bq * 2 + bi;
        #pragma unroll
        for (int j = 0; j < 4; j++) {
            int n = nbase + tx * 4 + j;
            out[(size_t)b * OUTW + 1 + n] = -sqrtf(acc[bi][j]);
        }
    }
}

extern "C" void kernel_launch(void* const* d_in, const int* in_sizes, int n_in,
                              void* d_out, int out_size) {
    const float* vfs   = (const float*)d_in[0];
    const float* p_lfs = (const float*)d_in[1];
    const float* n_lfs = (const float*)d_in[2];
    const float* W_h   = (const float*)d_in[3];
    const float* b_h   = (const float*)d_in[4];
    const float* W_e   = (const float*)d_in[5];
    const float* b_e   = (const float*)d_in[6];
    float* out = (float*)d_out;

    float* part = nullptr;
    float* hidden = nullptr;
    cudaGetSymbolAddress((void**)&part, g_part);
    cudaGetSymbolAddress((void**)&hidden, g_hidden);

    const int SMEM_BYTES = STAGES * 2 * 128 * LDS_SM * 4;   // 110592
    static bool attr_set = false;
    if (!attr_set) {
        cudaFuncSetAttribute(wmma_gemm, cudaFuncAttributeMaxDynamicSharedMemorySize, SMEM_BYTES);
        attr_set = true;
    }

    // GEMM1: part[4][128][4096] = vfs @ W_h^T  (tf32 WMMA + cp.async, K-split 4)
    wmma_gemm<<<dim3(KDIM / 128, 4), 256, SMEM_BYTES>>>(vfs, W_h, part, KDIM, KDIM / 4);
    reduce_hidden<<<512, 256>>>(b_h);
    // GEMM2: part[16][128][512] = hidden @ W_e^T (K-split 16 -> 64 CTAs)
    wmma_gemm<<<dim3(EMB / 128, 16), 256, SMEM_BYTES>>>(hidden, W_e, part, EMB, KDIM / 16);
    reduce_emb<<<64, 256>>>(b_e);
    // scores (bx==16 blocks do positive scores)
    nscore_kernel<<<dim3(NNEG / 128 + 1, B_SZ / 16), 256>>>(n_lfs, p_lfs, out);
}

// round 7
// speedup vs baseline: 2.9408x; 1.1248x over previous
#include <cuda_runtime.h>
#include <mma.h>
#include <math.h>
#include <cstdint>

using namespace nvcuda;

#define B_SZ   128
#define KDIM   4096
#define EMB    512
#define NNEG   2048
#define OUTW   (NNEG + 1)

#define STAGES 2
#define BK     32
#define LDS_SM 36    // padded row length in floats (144B, 16B-aligned)

// Scratch (static device globals — no allocation).
__device__ float g_part[4 * 1024 * 1024];    // 16 MB (split-K partials, reused)
__device__ float g_hidden[B_SZ * KDIM];      // 2 MB
__device__ float g_emb[B_SZ * EMB];          // 256 KB

__device__ __forceinline__ uint32_t smem_u32(const void* p) {
    uint32_t a;
    asm("{ .reg .u64 t; cvta.to.shared.u64 t, %1; cvt.u32.u64 %0, t; }" : "=r"(a) : "l"(p));
    return a;
}

// ---------------------------------------------------------------------------
// tf32 WMMA split-K GEMM with cp.async 2-stage pipeline, 2 CTAs/SM.
// Cpart[sk][128, N] = A[128, ksl] @ B[N, ksl]^T
// A [128, KDIM] f32 row-major, B [N, KDIM] f32 row-major (PyTorch W layout).
// BM=128, BN=128, BK=32, 256 threads (8 warps 2x4), warp tile 64x32.
// tf32 inputs are fed as raw f32 (HW truncates mantissa — no cvt on the
// critical path; rel_err watched).
// ---------------------------------------------------------------------------
__device__ __forceinline__ void issue_stage(float* smem, int s,
    const float* __restrict__ A, const float* __restrict__ B,
    int k0, int tid, int nbase, bool active)
{
    if (active) {
        float* sA = smem + s * (2 * 128 * LDS_SM);
        float* sB = sA + 128 * LDS_SM;
        #pragma unroll
        for (int i = 0; i < 4; i++) {
            int c = tid + i * 256;               // 0..1023 chunk id
            int row = c >> 3;
            int seg = (c & 7) << 2;              // float offset of 16B chunk
            const float* ga = &A[(size_t)row * KDIM + k0 + seg];
            const float* gb = &B[(size_t)(nbase + row) * KDIM + k0 + seg];
            uint32_t da = smem_u32(&sA[row * LDS_SM + seg]);
            uint32_t db = smem_u32(&sB[row * LDS_SM + seg]);
            asm volatile("cp.async.cg.shared.global [%0], [%1], 16;" :: "r"(da), "l"(ga) : "memory");
            asm volatile("cp.async.cg.shared.global [%0], [%1], 16;" :: "r"(db), "l"(gb) : "memory");
        }
    }
    asm volatile("cp.async.commit_group;" ::: "memory");
}

__global__ void __launch_bounds__(256, 2)
wmma_gemm(const float* __restrict__ A, const float* __restrict__ B,
          float* __restrict__ C, int ldc, int k_len)
{
    extern __shared__ float smem[];
    const int tid = threadIdx.x;
    const int wid = tid >> 5;
    const int wm = wid >> 2;            // m offset 64*wm
    const int wn = wid & 3;             // n offset 32*wn
    const int nbase = blockIdx.x * 128;
    const int k_lo = blockIdx.y * k_len;
    float* __restrict__ Cout = C + (size_t)blockIdx.y * 128u * (size_t)ldc;

    wmma::fragment<wmma::accumulator, 16, 16, 8, float> acc[4][2];
    #pragma unroll
    for (int i = 0; i < 4; i++)
        #pragma unroll
        for (int j = 0; j < 2; j++) wmma::fill_fragment(acc[i][j], 0.0f);

    const int nIter = k_len / BK;

    // prologue: issue STAGES-1 stages
    #pragma unroll
    for (int s = 0; s < STAGES - 1; s++)
        issue_stage(smem, s, A, B, k_lo + s * BK, tid, nbase, s < nIter);

    for (int it = 0; it < nIter; it++) {
        int ns = it + STAGES - 1;
        issue_stage(smem, ns % STAGES, A, B, k_lo + ns * BK, tid, nbase, ns < nIter);
        asm volatile("cp.async.wait_group %0;" :: "n"(STAGES - 1) : "memory");
        __syncthreads();

        float* sA = smem + (it % STAGES) * (2 * 128 * LDS_SM);
        float* sB = sA + 128 * LDS_SM;
        #pragma unroll
        for (int ks = 0; ks < BK / 8; ks++) {
            int k0 = ks * 8;
            wmma::fragment<wmma::matrix_a, 16, 16, 8, wmma::precision::tf32, wmma::row_major> af[4];
            wmma::fragment<wmma::matrix_b, 16, 16, 8, wmma::precision::tf32, wmma::col_major> bf[2];
            #pragma unroll
            for (int i = 0; i < 4; i++)
                wmma::load_matrix_sync(af[i], &sA[(wm * 64 + i * 16) * LDS_SM + k0], LDS_SM);
            #pragma unroll
            for (int j = 0; j < 2; j++)
                wmma::load_matrix_sync(bf[j], &sB[(wn * 32 + j * 16) * LDS_SM + k0], LDS_SM);
            #pragma unroll
            for (int i = 0; i < 4; i++)
                #pragma unroll
                for (int j = 0; j < 2; j++)
                    wmma::mma_sync(acc[i][j], af[i], bf[j], acc[i][j]);
        }
        __syncthreads();
    }

    #pragma unroll
    for (int i = 0; i < 4; i++)
        #pragma unroll
        for (int j = 0; j < 2; j++) {
            int m0 = wm * 64 + i * 16;
            int n0 = nbase + wn * 32 + j * 16;
            wmma::store_matrix_sync(&Cout[(size_t)m0 * ldc + n0], acc[i][j], ldc,
                                    wmma::mem_row_major);
        }
}

// hidden = sum_{sk<8} part[sk] + b_h  (float4, 512 blocks)
__global__ void reduce_hidden(const float* __restrict__ b_h) {
    int i4 = blockIdx.x * blockDim.x + threadIdx.x;     // < 131072
    float4 s = ((const float4*)b_h)[i4 & (KDIM / 4 - 1)];
    #pragma unroll
    for (int k = 0; k < 8; k++) {
        float4 v = *(const float4*)&g_part[(size_t)k * (B_SZ * KDIM) + i4 * 4];
        s.x += v.x; s.y += v.y; s.z += v.z; s.w += v.w;
    }
    ((float4*)g_hidden)[i4] = s;
}

// emb = sum_{sk<32} part[sk] + b_e  (float4, 64 blocks)
__global__ void reduce_emb(const float* __restrict__ b_e) {
    int i4 = blockIdx.x * blockDim.x + threadIdx.x;     // < 16384
    float4 s = ((const float4*)b_e)[i4 & (EMB / 4 - 1)];
    #pragma unroll
    for (int k = 0; k < 32; k++) {
        float4 v = *(const float4*)&g_part[(size_t)k * (B_SZ * EMB) + i4 * 4];
        s.x += v.x; s.y += v.y; s.z += v.z; s.w += v.w;
    }
    ((float4*)g_emb)[i4] = s;
}

// out[b, 1+n] = -||relu(n_lfs[n] - emb[b])|| ; blocks with bx==16 do the
// positive scores out[b,0] = -||relu(p_lfs[b] - emb[b])|| instead.
__global__ void __launch_bounds__(256, 2)
nscore_kernel(const float* __restrict__ n_lfs, const float* __restrict__ p_lfs,
              float* __restrict__ out) {
    const int tid = threadIdx.x;
    const int btile = blockIdx.y * 16;

    if (blockIdx.x == 16) {   // positive-score path: 8 warps x 2 b each
        int wq = tid >> 5, lane = tid & 31;
        #pragma unroll
        for (int r = 0; r < 2; r++) {
            int b = btile + wq * 2 + r;
            const float* pp = p_lfs + (size_t)b * EMB;
            const float* ee = g_emb + (size_t)b * EMB;
            float s = 0.f;
            #pragma unroll
            for (int j = 0; j < 4; j++) {
                int d = j * 128 + lane * 4;
                float4 p = *(const float4*)&pp[d];
                float4 e = *(const float4*)&ee[d];
                float r0 = fmaxf(p.x - e.x, 0.f), r1 = fmaxf(p.y - e.y, 0.f);
                float r2 = fmaxf(p.z - e.z, 0.f), r3 = fmaxf(p.w - e.w, 0.f);
                s = fmaf(r0, r0, s); s = fmaf(r1, r1, s);
                s = fmaf(r2, r2, s); s = fmaf(r3, r3, s);
            }
            #pragma unroll
            for (int off = 16; off > 0; off >>= 1) s += __shfl_down_sync(0xffffffffu, s, off);
            if (lane == 0) out[(size_t)b * OUTW] = -sqrtf(s);
        }
        return;
    }

    __shared__ float Ns[32][128 + 4];
    __shared__ float Es[16][32];
    const int tx = tid & 31;
    const int bq = tid >> 5;
    const int nbase = blockIdx.x * 128;

    float acc[2][4] = {};
    float4 nR[4];
    float4 eR = make_float4(0.f, 0.f, 0.f, 0.f);

    #pragma unroll
    for (int i = 0; i < 4; i++) {
        int f = tid + i * 256;
        int row = f >> 3, dv = (f & 7) << 2;
        nR[i] = *(const float4*)&n_lfs[(size_t)(nbase + row) * EMB + dv];
    }
    if (tid < 128) {
        int row = tid >> 3, dv = (tid & 7) << 2;
        eR = *(const float4*)&g_emb[(size_t)(btile + row) * EMB + dv];
    }

    for (int it = 0; it < 16; it++) {
        #pragma unroll
        for (int i = 0; i < 4; i++) {
            int f = tid + i * 256;
            int row = f >> 3, dv = (f & 7) << 2;
            Ns[dv + 0][row] = nR[i].x; Ns[dv + 1][row] = nR[i].y;
            Ns[dv + 2][row] = nR[i].z; Ns[dv + 3][row] = nR[i].w;
        }
        if (tid < 128) {
            int row = tid >> 3, dv = (tid & 7) << 2;
            *(float4*)&Es[row][dv] = eR;
        }
        __syncthreads();
        if (it + 1 < 16) {
            int dc = (it + 1) * 32;
            #pragma unroll
            for (int i = 0; i < 4; i++) {
                int f = tid + i * 256;
                int row = f >> 3, dv = (f & 7) << 2;
                nR[i] = *(const float4*)&n_lfs[(size_t)(nbase + row) * EMB + dc + dv];
            }
            if (tid < 128) {
                int row = tid >> 3, dv = (tid & 7) << 2;
                eR = *(const float4*)&g_emb[(size_t)(btile + row) * EMB + dc + dv];
            }
        }
        #pragma unroll 8
        for (int d = 0; d < 32; d++) {
            float e0 = Es[bq * 2 + 0][d];
            float e1 = Es[bq * 2 + 1][d];
            float4 nv = *(const float4*)&Ns[d][tx * 4];
            float r;
            r = fmaxf(nv.x - e0, 0.f); acc[0][0] = fmaf(r, r, acc[0][0]);
            r = fmaxf(nv.y - e0, 0.f); acc[0][1] = fmaf(r, r, acc[0][1]);
            r = fmaxf(nv.z - e0, 0.f); acc[0][2] = fmaf(r, r, acc[0][2]);
            r = fmaxf(nv.w - e0, 0.f); acc[0][3] = fmaf(r, r, acc[0][3]);
            r = fmaxf(nv.x - e1, 0.f); acc[1][0] = fmaf(r, r, acc[1][0]);
            r = fmaxf(nv.y - e1, 0.f); acc[1][1] = fmaf(r, r, acc[1][1]);
            r = fmaxf(nv.z - e1, 0.f); acc[1][2] = fmaf(r, r, acc[1][2]);
            r = fmaxf(nv.w - e1, 0.f); acc[1][3] = fmaf(r, r, acc[1][3]);
        }
        __syncthreads();
    }

    #pragma unroll
    for (int bi = 0; bi < 2; bi++) {
        int b = btile + bq * 2 + bi;
        #pragma unroll
        for (int j = 0; j < 4; j++) {
            int n = nbase + tx * 4 + j;
            out[(size_t)b * OUTW + 1 + n] = -sqrtf(acc[bi][j]);
        }
    }
}

extern "C" void kernel_launch(void* const* d_in, const int* in_sizes, int n_in,
                              void* d_out, int out_size) {
    const float* vfs   = (const float*)d_in[0];
    const float* p_lfs = (const float*)d_in[1];
    const float* n_lfs = (const float*)d_in[2];
    const float* W_h   = (const float*)d_in[3];
    const float* b_h   = (const float*)d_in[4];
    const float* W_e   = (const float*)d_in[5];
    const float* b_e   = (const float*)d_in[6];
    float* out = (float*)d_out;

    float* part = nullptr;
    float* hidden = nullptr;
    cudaGetSymbolAddress((void**)&part, g_part);
    cudaGetSymbolAddress((void**)&hidden, g_hidden);

    const int SMEM_BYTES = STAGES * 2 * 128 * LDS_SM * 4;   // 73728
    static bool attr_set = false;
    if (!attr_set) {
        cudaFuncSetAttribute(wmma_gemm, cudaFuncAttributeMaxDynamicSharedMemorySize, SMEM_BYTES);
        attr_set = true;
    }

    // GEMM1: part[8][128][4096] = vfs @ W_h^T  (tf32 WMMA + cp.async, K-split 8)
    wmma_gemm<<<dim3(KDIM / 128, 8), 256, SMEM_BYTES>>>(vfs, W_h, part, KDIM, KDIM / 8);
    reduce_hidden<<<512, 256>>>(b_h);
    // GEMM2: part[32][128][512] = hidden @ W_e^T (K-split 32 -> 128 CTAs)
    wmma_gemm<<<dim3(EMB / 128, 32), 256, SMEM_BYTES>>>(hidden, W_e, part, EMB, KDIM / 32);
    reduce_emb<<<64, 256>>>(b_e);
    // scores (bx==16 blocks do positive scores)
    nscore_kernel<<<dim3(NNEG / 128 + 1, B_SZ / 16), 256>>>(n_lfs, p_lfs, out);
}

// round 9
// speedup vs baseline: 4.3235x; 1.4702x over previous
#include <cuda_runtime.h>
#include <cuda_fp16.h>
#include <mma.h>
#include <math.h>
#include <cstdint>

using namespace nvcuda;

#define B_SZ   128
#define KDIM   4096
#define EMB    512
#define NNEG   2048
#define OUTW   (NNEG + 1)

#define BK     32
#define LDH    40    // padded half-row (80B, LDSM-friendly, mult of 8)

// Scratch (static device globals — no allocation).
__device__ float g_part[4 * 1024 * 1024];    // 16 MB (split-K partials, reused)
__device__ float g_hidden[B_SZ * KDIM];      // 2 MB
__device__ float g_emb[B_SZ * EMB];          // 256 KB

__device__ __forceinline__ uint32_t h2_bits(__half2 h) {
    return *reinterpret_cast<uint32_t*>(&h);
}

// ---------------------------------------------------------------------------
// fp16 WMMA split-K GEMM, fp32 accumulate, 2-stage SMEM double buffer with
// register prefetch (LDG f32 -> cvt.rn f16x2 -> STS), 2 CTAs/SM.
// Cpart[sk][128, N] = A[128, ksl] @ B[N, ksl]^T
// BM=128, BN=128, BK=32, 256 threads (8 warps 2x4), warp tile 64x32.
// ---------------------------------------------------------------------------
__device__ __forceinline__ void ldg_cvt(uint32_t* ra, uint32_t* rb,
    const float* __restrict__ A, const float* __restrict__ B,
    int k0, int tid, int nbase)
{
    const int row = tid >> 1;
    const int seg = (tid & 1) << 4;        // 0 or 16 floats
    const float* pa = &A[(size_t)row * KDIM + k0 + seg];
    const float* pb = &B[(size_t)(nbase + row) * KDIM + k0 + seg];
    #pragma unroll
    for (int i = 0; i < 4; i++) {
        float4 va = *(const float4*)(pa + i * 4);
        float4 vb = *(const float4*)(pb + i * 4);
        ra[i * 2 + 0] = h2_bits(__floats2half2_rn(va.x, va.y));
        ra[i * 2 + 1] = h2_bits(__floats2half2_rn(va.z, va.w));
        rb[i * 2 + 0] = h2_bits(__floats2half2_rn(vb.x, vb.y));
        rb[i * 2 + 1] = h2_bits(__floats2half2_rn(vb.z, vb.w));
    }
}

__device__ __forceinline__ void sts_tile(__half* sA, __half* sB,
    const uint32_t* ra, const uint32_t* rb, int tid)
{
    const int row = tid >> 1;
    const int seg = (tid & 1) << 4;        // halves offset
    *(uint4*)&sA[row * LDH + seg]     = make_uint4(ra[0], ra[1], ra[2], ra[3]);
    *(uint4*)&sA[row * LDH + seg + 8] = make_uint4(ra[4], ra[5], ra[6], ra[7]);
    *(uint4*)&sB[row * LDH + seg]     = make_uint4(rb[0], rb[1], rb[2], rb[3]);
    *(uint4*)&sB[row * LDH + seg + 8] = make_uint4(rb[4], rb[5], rb[6], rb[7]);
}

__global__ void __launch_bounds__(256, 2)
hgemm(const float* __restrict__ A, const float* __restrict__ B,
      float* __restrict__ C, int ldc, int k_len)
{
    __shared__ __align__(16) __half sA[2][128 * LDH];
    __shared__ __align__(16) __half sB[2][128 * LDH];

    const int tid = threadIdx.x;
    const int wid = tid >> 5;
    const int wm = wid >> 2;            // m offset 64*wm
    const int wn = wid & 3;             // n offset 32*wn
    const int nbase = blockIdx.x * 128;
    const int k_lo = blockIdx.y * k_len;
    float* __restrict__ Cout = C + (size_t)blockIdx.y * 128u * (size_t)ldc;

    wmma::fragment<wmma::accumulator, 16, 16, 16, float> acc[4][2];
    #pragma unroll
    for (int i = 0; i < 4; i++)
        #pragma unroll
        for (int j = 0; j < 2; j++) wmma::fill_fragment(acc[i][j], 0.0f);

    const int nIter = k_len / BK;
    uint32_t ra[8], rb[8];

    ldg_cvt(ra, rb, A, B, k_lo, tid, nbase);
    sts_tile(sA[0], sB[0], ra, rb, tid);
    __syncthreads();

    for (int it = 0; it < nIter; it++) {
        const int p = it & 1;
        if (it + 1 < nIter)
            ldg_cvt(ra, rb, A, B, k_lo + (it + 1) * BK, tid, nbase);   // in flight

        #pragma unroll
        for (int ks = 0; ks < 2; ks++) {
            const int k0 = ks * 16;
            wmma::fragment<wmma::matrix_a, 16, 16, 16, __half, wmma::row_major> af[4];
            wmma::fragment<wmma::matrix_b, 16, 16, 16, __half, wmma::col_major> bf[2];
            #pragma unroll
            for (int i = 0; i < 4; i++)
                wmma::load_matrix_sync(af[i], &sA[p][(wm * 64 + i * 16) * LDH + k0], LDH);
            #pragma unroll
            for (int j = 0; j < 2; j++)
                wmma::load_matrix_sync(bf[j], &sB[p][(wn * 32 + j * 16) * LDH + k0], LDH);
            #pragma unroll
            for (int i = 0; i < 4; i++)
                #pragma unroll
                for (int j = 0; j < 2; j++)
                    wmma::mma_sync(acc[i][j], af[i], bf[j], acc[i][j]);
        }

        if (it + 1 < nIter) {
            __syncthreads();
            sts_tile(sA[p ^ 1], sB[p ^ 1], ra, rb, tid);
            __syncthreads();
        }
    }

    #pragma unroll
    for (int i = 0; i < 4; i++)
        #pragma unroll
        for (int j = 0; j < 2; j++) {
            int m0 = wm * 64 + i * 16;
            int n0 = nbase + wn * 32 + j * 16;
            wmma::store_matrix_sync(&Cout[(size_t)m0 * ldc + n0], acc[i][j], ldc,
                                    wmma::mem_row_major);
        }
}

// hidden = sum_{sk<8} part[sk] + b_h  (float4, 512 blocks x 256 thr)
__global__ void __launch_bounds__(256) reduce_hidden(const float* __restrict__ b_h) {
    int i4 = blockIdx.x * blockDim.x + threadIdx.x;     // < 131072
    float4 s = ((const float4*)b_h)[i4 & (KDIM / 4 - 1)];
    #pragma unroll
    for (int k = 0; k < 8; k++) {
        float4 v = *(const float4*)&g_part[(size_t)k * (B_SZ * KDIM) + i4 * 4];
        s.x += v.x; s.y += v.y; s.z += v.z; s.w += v.w;
    }
    ((float4*)g_hidden)[i4] = s;
}

// emb = sum_{sk<32} part[sk] + b_e  — two-level: 4 sk-groups of 8 per block.
// 256 blocks x 256 thr; each block produces 64 float4 outputs.
__global__ void __launch_bounds__(256) reduce_emb(const float* __restrict__ b_e) {
    __shared__ float4 red[256];
    const int o = blockIdx.x * 64 + (threadIdx.x & 63);   // float4 output index
    const int g = threadIdx.x >> 6;                       // sk-group 0..3
    float4 s = make_float4(0.f, 0.f, 0.f, 0.f);
    #pragma unroll
    for (int k = 0; k < 8; k++) {
        float4 v = *(const float4*)&g_part[(size_t)(g * 8 + k) * (B_SZ * EMB) + o * 4];
        s.x += v.x; s.y += v.y; s.z += v.z; s.w += v.w;
    }
    red[threadIdx.x] = s;
    __syncthreads();
    if (g == 0) {
        float4 a = red[threadIdx.x];
        float4 b = red[threadIdx.x + 64];
        float4 c = red[threadIdx.x + 128];
        float4 d = red[threadIdx.x + 192];
        float4 bias = ((const float4*)b_e)[o & (EMB / 4 - 1)];
        float4 r = make_float4(a.x + b.x + c.x + d.x + bias.x,
                               a.y + b.y + c.y + d.y + bias.y,
                               a.z + b.z + c.z + d.z + bias.z,
                               a.w + b.w + c.w + d.w + bias.w);
        ((float4*)g_emb)[o] = r;
    }
}

// out[b, 1+n] = -||relu(n_lfs[n] - emb[b])|| ; blocks with bx==16 do the
// positive scores out[b,0] = -||relu(p_lfs[b] - emb[b])|| instead.
__global__ void __launch_bounds__(256, 2)
nscore_kernel(const float* __restrict__ n_lfs, const float* __restrict__ p_lfs,
              float* __restrict__ out) {
    const int tid = threadIdx.x;
    const int btile = blockIdx.y * 16;

    if (blockIdx.x == 16) {   // positive-score path: 8 warps x 2 b each
        int wq = tid >> 5, lane = tid & 31;
        #pragma unroll
        for (int r = 0; r < 2; r++) {
            int b = btile + wq * 2 + r;
            const float* pp = p_lfs + (size_t)b * EMB;
            const float* ee = g_emb + (size_t)b * EMB;
            float s = 0.f;
            #pragma unroll
            for (int j = 0; j < 4; j++) {
                int d = j * 128 + lane * 4;
                float4 p = *(const float4*)&pp[d];
                float4 e = *(const float4*)&ee[d];
                float r0 = fmaxf(p.x - e.x, 0.f), r1 = fmaxf(p.y - e.y, 0.f);
                float r2 = fmaxf(p.z - e.z, 0.f), r3 = fmaxf(p.w - e.w, 0.f);
                s = fmaf(r0, r0, s); s = fmaf(r1, r1, s);
                s = fmaf(r2, r2, s); s = fmaf(r3, r3, s);
            }
            #pragma unroll
            for (int off = 16; off > 0; off >>= 1) s += __shfl_down_sync(0xffffffffu, s, off);
            if (lane == 0) out[(size_t)b * OUTW] = -sqrtf(s);
        }
        return;
    }

    __shared__ float Ns[32][128 + 4];
    __shared__ float Es[16][32];
    const int tx = tid & 31;
    const int bq = tid >> 5;
    const int nbase = blockIdx.x * 128;

    float acc[2][4] = {};
    float4 nR[4];
    float4 eR = make_float4(0.f, 0.f, 0.f, 0.f);

    #pragma unroll
    for (int i = 0; i < 4; i++) {
        int f = tid + i * 256;
        int row = f >> 3, dv = (f & 7) << 2;
        nR[i] = *(const float4*)&n_lfs[(size_t)(nbase + row) * EMB + dv];
    }
    if (tid < 128) {
        int row = tid >> 3, dv = (tid & 7) << 2;
        eR = *(const float4*)&g_emb[(size_t)(btile + row) * EMB + dv];
    }

    for (int it = 0; it < 16; it++) {
        #pragma unroll
        for (int i = 0; i < 4; i++) {
            int f = tid + i * 256;
            int row = f >> 3, dv = (f & 7) << 2;
            Ns[dv + 0][row] = nR[i].x; Ns[dv + 1][row] = nR[i].y;
            Ns[dv + 2][row] = nR[i].z; Ns[dv + 3][row] = nR[i].w;
        }
        if (tid < 128) {
            int row = tid >> 3, dv = (tid & 7) << 2;
            *(float4*)&Es[row][dv] = eR;
        }
        __syncthreads();
        if (it + 1 < 16) {
            int dc = (it + 1) * 32;
            #pragma unroll
            for (int i = 0; i < 4; i++) {
                int f = tid + i * 256;
                int row = f >> 3, dv = (f & 7) << 2;
                nR[i] = *(const float4*)&n_lfs[(size_t)(nbase + row) * EMB + dc + dv];
            }
            if (tid < 128) {
                int row = tid >> 3, dv = (tid & 7) << 2;
                eR = *(const float4*)&g_emb[(size_t)(btile + row) * EMB + dc + dv];
            }
        }
        #pragma unroll 8
        for (int d = 0; d < 32; d++) {
            float e0 = Es[bq * 2 + 0][d];
            float e1 = Es[bq * 2 + 1][d];
            float4 nv = *(const float4*)&Ns[d][tx * 4];
            float r;
            r = fmaxf(nv.x - e0, 0.f); acc[0][0] = fmaf(r, r, acc[0][0]);
            r = fmaxf(nv.y - e0, 0.f); acc[0][1] = fmaf(r, r, acc[0][1]);
            r = fmaxf(nv.z - e0, 0.f); acc[0][2] = fmaf(r, r, acc[0][2]);
            r = fmaxf(nv.w - e0, 0.f); acc[0][3] = fmaf(r, r, acc[0][3]);
            r = fmaxf(nv.x - e1, 0.f); acc[1][0] = fmaf(r, r, acc[1][0]);
            r = fmaxf(nv.y - e1, 0.f); acc[1][1] = fmaf(r, r, acc[1][1]);
            r = fmaxf(nv.z - e1, 0.f); acc[1][2] = fmaf(r, r, acc[1][2]);
            r = fmaxf(nv.w - e1, 0.f); acc[1][3] = fmaf(r, r, acc[1][3]);
        }
        __syncthreads();
    }

    #pragma unroll
    for (int bi = 0; bi < 2; bi++) {
        int b = btile + bq * 2 + bi;
        #pragma unroll
        for (int j = 0; j < 4; j++) {
            int n = nbase + tx * 4 + j;
            out[(size_t)b * OUTW + 1 + n] = -sqrtf(acc[bi][j]);
        }
    }
}

extern "C" void kernel_launch(void* const* d_in, const int* in_sizes, int n_in,
                              void* d_out, int out_size) {
    const float* vfs   = (const float*)d_in[0];
    const float* p_lfs = (const float*)d_in[1];
    const float* n_lfs = (const float*)d_in[2];
    const float* W_h   = (const float*)d_in[3];
    const float* b_h   = (const float*)d_in[4];
    const float* W_e   = (const float*)d_in[5];
    const float* b_e   = (const float*)d_in[6];
    float* out = (float*)d_out;

    float* part = nullptr;
    float* hidden = nullptr;
    cudaGetSymbolAddress((void**)&part, g_part);
    cudaGetSymbolAddress((void**)&hidden, g_hidden);

    // GEMM1: part[8][128][4096] = vfs @ W_h^T  (fp16 WMMA, K-split 8 -> 256 CTAs)
    hgemm<<<dim3(KDIM / 128, 8), 256>>>(vfs, W_h, part, KDIM, KDIM / 8);
    reduce_hidden<<<512, 256>>>(b_h);
    // GEMM2: part[32][128][512] = hidden @ W_e^T (K-split 32 -> 128 CTAs)
    hgemm<<<dim3(EMB / 128, 32), 256>>>(hidden, W_e, part, EMB, KDIM / 32);
    reduce_emb<<<256, 256>>>(b_e);
    // scores (bx==16 blocks do positive scores)
    nscore_kernel<<<dim3(NNEG / 128 + 1, B_SZ / 16), 256>>>(n_lfs, p_lfs, out);
}